// round 15
// baseline (speedup 1.0000x reference)
#include <cuda_runtime.h>

#define BB 16
#define LL 192
#define EE 128
#define TT 25
#define NI (LL - TT - 1)            // 166
#define OUT_L (TT + 1 + NI * LL)    // 31898
#define E4 (EE / 4)                 // 32 float4 per row
#define TPB 256
#define WARPS (TPB / 32)            // 8
#define L_RANGE 16                  // l-rows per CTA
#define LSPLITS (LL / L_RANGE)      // 12
#define NPASS (L_RANGE / WARPS)     // 2  -> 8 s-regs/thread
#define I_PER_BLK 12
#define ICH ((NI + I_PER_BLK - 1) / I_PER_BLK)  // 14
#define HEAD4 ((TT + 1) * E4)       // 832 float4 of head rows per batch
#define HEAD_PER_Y ((HEAD4 + LSPLITS - 1) / LSPLITS)  // 70

// sigmoid(z) = 0.5*tanh(z/2) + 0.5  -> single MUFU op (tanh.approx.f32)
__device__ __forceinline__ float fast_sigmoid_half(float zhalf) {
    float t;
    asm("tanh.approx.f32 %0, %1;" : "=f"(t) : "f"(zhalf));
    return fmaf(0.5f, t, 0.5f);
}

// ---------------------------------------------------------------------------
// Single fused kernel (converged configuration):
//   blocks[b,i,l,e] = xp + s0[b,l,e]*(xi-xp)
//   s0 = sigmoid(x*(W0-W1) + (b0-b1)); xi = x[b,i+T+1,e], xp = x[b,i+1,e]
// Mapped-optimal levers: grid (14,12,16)=2688 CTAs of 256 thr, 6 CTAs/SM
// (occupancy knee), tanh.approx fused sigmoid (~1.1us chip-wide), 2-stage
// xi/xp prefetch (load-bearing), 32-bit pointer-increment addressing,
// warp-coalesced 512B streaming STG.128 rows, balanced head copy.
// This round: peeled final iteration -> unconditional prefetch in the main
// loop (no per-iter predicates, tighter scheduling).
// ---------------------------------------------------------------------------
__global__ void __launch_bounds__(TPB, 6)
fused_kernel(const float* __restrict__ x,
             const float* __restrict__ W,
             const float* __restrict__ bv,
             float* __restrict__ out) {
    const int b  = blockIdx.z;
    const int l0 = blockIdx.y * L_RANGE;
    const int e4 = threadIdx.x & (E4 - 1);     // 0..31, contiguous in warp
    const int w  = threadIdx.x >> 5;           // 0..7, constant in warp

    const float4* xb = reinterpret_cast<const float4*>(x) + b * (LL * E4);
    float4* o4 = reinterpret_cast<float4*>(out);

    // Head copy: out[b, 0:26, :] = x[b, 0:26, :], split across the 12 y-CTAs
    if (blockIdx.x == 0) {
        const unsigned ob = (unsigned)b * (OUT_L * E4);
        const int k0 = blockIdx.y * HEAD_PER_Y;
        const int k1 = min(k0 + HEAD_PER_Y, HEAD4);
        for (int k = k0 + (int)threadIdx.x; k < k1; k += TPB)
            __stcs(o4 + ob + k, xb[k]);
    }

    // Inline sigmoid for this thread's 2 s-float4 (i-invariant within CTA).
    // Fold the /2 of tanh-sigmoid into the affine: zhalf = x*dW2 + db2.
    const float dW2 = 0.5f * (W[0] - W[1]);
    const float db2 = 0.5f * (bv[0] - bv[1]);
    float4 s[NPASS];
    #pragma unroll
    for (int p = 0; p < NPASS; p++) {
        float4 xv = xb[(l0 + w + p * WARPS) * E4 + e4];
        s[p].x = fast_sigmoid_half(fmaf(xv.x, dW2, db2));
        s[p].y = fast_sigmoid_half(fmaf(xv.y, dW2, db2));
        s[p].z = fast_sigmoid_half(fmaf(xv.z, dW2, db2));
        s[p].w = fast_sigmoid_half(fmaf(xv.w, dW2, db2));
    }

    const int i0 = blockIdx.x * I_PER_BLK;
    const int iend = min(i0 + I_PER_BLK, NI);
    if (i0 >= iend) return;
    const int n_iter = iend - i0;

    // Hot-loop pointers: advance by constants per i (no per-i multiplies).
    // 32-bit offsets: max out index = 16*31898*32 = 16.3M < 2^31.
    const float4* pxi = xb + (i0 + TT + 1) * E4 + e4;
    const float4* pxp = xb + (i0 + 1) * E4 + e4;
    float4* po = o4 + ((unsigned)b * (OUT_L * E4)
                       + (unsigned)((TT + 1) + i0 * LL + l0 + w) * E4 + e4);

    // 2-stage pipeline on xi/xp (load-bearing — do not remove)
    float4 xi = *pxi;
    float4 xp = *pxp;

    // Main loop: n_iter-1 iterations with UNCONDITIONAL prefetch (peeled tail)
    for (int it = 0; it < n_iter - 1; it++) {
        float4 nxi = pxi[E4];
        float4 nxp = pxp[E4];
        pxi += E4; pxp += E4;

        float4 d;
        d.x = xi.x - xp.x; d.y = xi.y - xp.y;
        d.z = xi.z - xp.z; d.w = xi.w - xp.w;

        #pragma unroll
        for (int p = 0; p < NPASS; p++) {
            float4 o;
            o.x = fmaf(s[p].x, d.x, xp.x);
            o.y = fmaf(s[p].y, d.y, xp.y);
            o.z = fmaf(s[p].z, d.z, xp.z);
            o.w = fmaf(s[p].w, d.w, xp.w);
            // write-once output: streaming store, evict-first in L2
            __stcs(po + p * (WARPS * E4), o);
        }
        po += (LL * E4);   // next i: advance one L-block

        xi = nxi; xp = nxp;
    }

    // Peeled final iteration (no prefetch)
    {
        float4 d;
        d.x = xi.x - xp.x; d.y = xi.y - xp.y;
        d.z = xi.z - xp.z; d.w = xi.w - xp.w;

        #pragma unroll
        for (int p = 0; p < NPASS; p++) {
            float4 o;
            o.x = fmaf(s[p].x, d.x, xp.x);
            o.y = fmaf(s[p].y, d.y, xp.y);
            o.z = fmaf(s[p].z, d.z, xp.z);
            o.w = fmaf(s[p].w, d.w, xp.w);
            __stcs(po + p * (WARPS * E4), o);
        }
    }
}

// ---------------------------------------------------------------------------
extern "C" void kernel_launch(void* const* d_in, const int* in_sizes, int n_in,
                              void* d_out, int out_size) {
    const float* x  = (const float*)d_in[0];  // (16,192,128) f32
    const float* W  = (const float*)d_in[1];  // (2,1) f32
    const float* bv = (const float*)d_in[2];  // (2,) f32
    float* out = (float*)d_out;               // (16,31898,128) f32

    dim3 grid(ICH, LSPLITS, BB);   // 14 x 12 x 16 = 2688 CTAs
    fused_kernel<<<grid, TPB>>>(x, W, bv, out);
}

// round 16
// speedup vs baseline: 1.0141x; 1.0141x over previous
#include <cuda_runtime.h>

#define BB 16
#define LL 192
#define EE 128
#define TT 25
#define NI (LL - TT - 1)            // 166
#define OUT_L (TT + 1 + NI * LL)    // 31898
#define E4 (EE / 4)                 // 32 float4 per row
#define TPB 256
#define WARPS (TPB / 32)            // 8
#define L_RANGE 16                  // l-rows per CTA
#define LSPLITS (LL / L_RANGE)      // 12
#define NPASS (L_RANGE / WARPS)     // 2  -> 8 s-regs/thread
#define I_PER_BLK 12
#define ICH ((NI + I_PER_BLK - 1) / I_PER_BLK)  // 14  (empirical optimum)
#define HEAD4 ((TT + 1) * E4)       // 832 float4 of head rows per batch
#define HEAD_PER_Y ((HEAD4 + LSPLITS - 1) / LSPLITS)  // 70

// sigmoid(z) = 0.5*tanh(z/2) + 0.5  -> single MUFU op (tanh.approx.f32)
__device__ __forceinline__ float fast_sigmoid_half(float zhalf) {
    float t;
    asm("tanh.approx.f32 %0, %1;" : "=f"(t) : "f"(zhalf));
    return fmaf(0.5f, t, 0.5f);
}

// ---------------------------------------------------------------------------
// Single fused kernel — CONVERGED CONFIGURATION (R12, best measured):
//   blocks[b,i,l,e] = xp + s0[b,l,e]*(xi-xp)
//   s0 = sigmoid(x*(W0-W1) + (b0-b1)); xi = x[b,i+T+1,e], xp = x[b,i+1,e]
// Empirically optimal on every mapped axis:
//  - grid (14,12,16)=2688 CTAs of 256 thr, launch_bounds(256,6): the
//    bandwidth-vs-occupancy knee (~44 warps/SM). More warps or fewer/larger
//    CTAs both measured worse (R7, R10, R13).
//  - tanh.approx fused sigmoid: 1 MUFU/elem, ~1.1us chip-wide (R9 win).
//  - CONDITIONAL 2-stage xi/xp prefetch: load-bearing; removal (R10) and
//    peeling (R15) both regressed — ptxas pipelines this exact form best.
//  - 32-bit pointer-increment addressing, streaming STG.128 (__stcs),
//    warp-coalesced 512B rows, head copy balanced over 12 y-CTAs (R12).
// Kernel wall: ~40.3us = 261MB @ ~5.06 TB/s effective write bandwidth.
// ---------------------------------------------------------------------------
__global__ void __launch_bounds__(TPB, 6)
fused_kernel(const float* __restrict__ x,
             const float* __restrict__ W,
             const float* __restrict__ bv,
             float* __restrict__ out) {
    const int b  = blockIdx.z;
    const int l0 = blockIdx.y * L_RANGE;
    const int e4 = threadIdx.x & (E4 - 1);     // 0..31, contiguous in warp
    const int w  = threadIdx.x >> 5;           // 0..7, constant in warp

    const float4* xb = reinterpret_cast<const float4*>(x) + b * (LL * E4);
    float4* o4 = reinterpret_cast<float4*>(out);

    // Head copy: out[b, 0:26, :] = x[b, 0:26, :], split across the 12 y-CTAs
    if (blockIdx.x == 0) {
        const unsigned ob = (unsigned)b * (OUT_L * E4);
        const int k0 = blockIdx.y * HEAD_PER_Y;
        const int k1 = min(k0 + HEAD_PER_Y, HEAD4);
        for (int k = k0 + (int)threadIdx.x; k < k1; k += TPB)
            __stcs(o4 + ob + k, xb[k]);
    }

    // Inline sigmoid for this thread's 2 s-float4 (i-invariant within CTA).
    // Fold the /2 of tanh-sigmoid into the affine: zhalf = x*dW2 + db2.
    const float dW2 = 0.5f * (W[0] - W[1]);
    const float db2 = 0.5f * (bv[0] - bv[1]);
    float4 s[NPASS];
    #pragma unroll
    for (int p = 0; p < NPASS; p++) {
        float4 xv = xb[(l0 + w + p * WARPS) * E4 + e4];
        s[p].x = fast_sigmoid_half(fmaf(xv.x, dW2, db2));
        s[p].y = fast_sigmoid_half(fmaf(xv.y, dW2, db2));
        s[p].z = fast_sigmoid_half(fmaf(xv.z, dW2, db2));
        s[p].w = fast_sigmoid_half(fmaf(xv.w, dW2, db2));
    }

    const int i0 = blockIdx.x * I_PER_BLK;
    const int iend = min(i0 + I_PER_BLK, NI);
    if (i0 >= iend) return;
    const int n_iter = iend - i0;

    // Hot-loop pointers: advance by constants per i (no per-i multiplies).
    // 32-bit offsets: max out index = 16*31898*32 = 16.3M < 2^31.
    const float4* pxi = xb + (i0 + TT + 1) * E4 + e4;
    const float4* pxp = xb + (i0 + 1) * E4 + e4;
    float4* po = o4 + ((unsigned)b * (OUT_L * E4)
                       + (unsigned)((TT + 1) + i0 * LL + l0 + w) * E4 + e4);

    // 2-stage pipeline on xi/xp (load-bearing — do not remove or peel)
    float4 xi = *pxi;
    float4 xp = *pxp;

    for (int it = 0; it < n_iter; it++) {
        float4 nxi, nxp;
        if (it + 1 < n_iter) {
            nxi = pxi[E4];
            nxp = pxp[E4];
        }
        pxi += E4; pxp += E4;

        float4 d;
        d.x = xi.x - xp.x; d.y = xi.y - xp.y;
        d.z = xi.z - xp.z; d.w = xi.w - xp.w;

        #pragma unroll
        for (int p = 0; p < NPASS; p++) {
            float4 o;
            o.x = fmaf(s[p].x, d.x, xp.x);
            o.y = fmaf(s[p].y, d.y, xp.y);
            o.z = fmaf(s[p].z, d.z, xp.z);
            o.w = fmaf(s[p].w, d.w, xp.w);
            // write-once output: streaming store, evict-first in L2
            __stcs(po + p * (WARPS * E4), o);
        }
        po += (LL * E4);   // next i: advance one L-block

        xi = nxi; xp = nxp;
    }
}

// ---------------------------------------------------------------------------
extern "C" void kernel_launch(void* const* d_in, const int* in_sizes, int n_in,
                              void* d_out, int out_size) {
    const float* x  = (const float*)d_in[0];  // (16,192,128) f32
    const float* W  = (const float*)d_in[1];  // (2,1) f32
    const float* bv = (const float*)d_in[2];  // (2,) f32
    float* out = (float*)d_out;               // (16,31898,128) f32

    dim3 grid(ICH, LSPLITS, BB);   // 14 x 12 x 16 = 2688 CTAs
    fused_kernel<<<grid, TPB>>>(x, W, bv, out);
}

// round 17
// speedup vs baseline: 1.0149x; 1.0007x over previous
#include <cuda_runtime.h>

#define BB 16
#define LL 192
#define EE 128
#define TT 25
#define NI (LL - TT - 1)            // 166
#define OUT_L (TT + 1 + NI * LL)    // 31898
#define E4 (EE / 4)                 // 32 float4 per row
#define TPB 256
#define WARPS (TPB / 32)            // 8
#define L_RANGE 16                  // l-rows per CTA
#define LSPLITS (LL / L_RANGE)      // 12
#define NPASS (L_RANGE / WARPS)     // 2  -> 8 s-regs/thread
#define I_PER_BLK 12
#define ICH ((NI + I_PER_BLK - 1) / I_PER_BLK)  // 14  (empirical optimum)
#define HEAD4 ((TT + 1) * E4)       // 832 float4 of head rows per batch
#define HEAD_PER_Y ((HEAD4 + LSPLITS - 1) / LSPLITS)  // 70

// sigmoid(z) = 0.5*tanh(z/2) + 0.5  -> single MUFU op (tanh.approx.f32)
__device__ __forceinline__ float fast_sigmoid_half(float zhalf) {
    float t;
    asm("tanh.approx.f32 %0, %1;" : "=f"(t) : "f"(zhalf));
    return fmaf(0.5f, t, 0.5f);
}

// ---------------------------------------------------------------------------
// Single fused kernel — CONVERGED FINAL CONFIGURATION:
//   blocks[b,i,l,e] = xp + s0[b,l,e]*(xi-xp)
//   s0 = sigmoid(x*(W0-W1) + (b0-b1)); xi = x[b,i+T+1,e], xp = x[b,i+1,e]
// Empirically optimal on every mapped axis (16 rounds of A/B on GB300):
//  - grid (14,12,16)=2688 CTAs of 256 thr, launch_bounds(256,6): the
//    bandwidth-vs-occupancy knee (~44 warps/SM). 96% occ, 512-thr CTAs,
//    and both finer/coarser i-granularity all measured worse.
//  - tanh.approx fused sigmoid: 1 MUFU/elem, ~1.1us chip-wide, absorbs the
//    former 3.3us split-kernel overhead at zero main-loop cost.
//  - CONDITIONAL 2-stage xi/xp prefetch: load-bearing; removing it (+8us)
//    or peeling it (+3.4us) both broke ptxas's software pipeline.
//  - 32-bit pointer-increment addressing, streaming STG.128 (__stcs)
//    protecting L2-resident x, warp-coalesced 512B rows, head copy
//    balanced over the 12 y-CTAs of each batch.
// Wall: 261MB output @ ~5.05 TB/s effective DRAM write bandwidth
// (~40.3us kernel) + ~2.7us fixed harness cost = ~43.0us total.
// ---------------------------------------------------------------------------
__global__ void __launch_bounds__(TPB, 6)
fused_kernel(const float* __restrict__ x,
             const float* __restrict__ W,
             const float* __restrict__ bv,
             float* __restrict__ out) {
    const int b  = blockIdx.z;
    const int l0 = blockIdx.y * L_RANGE;
    const int e4 = threadIdx.x & (E4 - 1);     // 0..31, contiguous in warp
    const int w  = threadIdx.x >> 5;           // 0..7, constant in warp

    const float4* xb = reinterpret_cast<const float4*>(x) + b * (LL * E4);
    float4* o4 = reinterpret_cast<float4*>(out);

    // Head copy: out[b, 0:26, :] = x[b, 0:26, :], split across the 12 y-CTAs
    if (blockIdx.x == 0) {
        const unsigned ob = (unsigned)b * (OUT_L * E4);
        const int k0 = blockIdx.y * HEAD_PER_Y;
        const int k1 = min(k0 + HEAD_PER_Y, HEAD4);
        for (int k = k0 + (int)threadIdx.x; k < k1; k += TPB)
            __stcs(o4 + ob + k, xb[k]);
    }

    // Inline sigmoid for this thread's 2 s-float4 (i-invariant within CTA).
    // Fold the /2 of tanh-sigmoid into the affine: zhalf = x*dW2 + db2.
    const float dW2 = 0.5f * (W[0] - W[1]);
    const float db2 = 0.5f * (bv[0] - bv[1]);
    float4 s[NPASS];
    #pragma unroll
    for (int p = 0; p < NPASS; p++) {
        float4 xv = xb[(l0 + w + p * WARPS) * E4 + e4];
        s[p].x = fast_sigmoid_half(fmaf(xv.x, dW2, db2));
        s[p].y = fast_sigmoid_half(fmaf(xv.y, dW2, db2));
        s[p].z = fast_sigmoid_half(fmaf(xv.z, dW2, db2));
        s[p].w = fast_sigmoid_half(fmaf(xv.w, dW2, db2));
    }

    const int i0 = blockIdx.x * I_PER_BLK;
    const int iend = min(i0 + I_PER_BLK, NI);
    if (i0 >= iend) return;
    const int n_iter = iend - i0;

    // Hot-loop pointers: advance by constants per i (no per-i multiplies).
    // 32-bit offsets: max out index = 16*31898*32 = 16.3M < 2^31.
    const float4* pxi = xb + (i0 + TT + 1) * E4 + e4;
    const float4* pxp = xb + (i0 + 1) * E4 + e4;
    float4* po = o4 + ((unsigned)b * (OUT_L * E4)
                       + (unsigned)((TT + 1) + i0 * LL + l0 + w) * E4 + e4);

    // 2-stage pipeline on xi/xp (load-bearing — do not remove or peel)
    float4 xi = *pxi;
    float4 xp = *pxp;

    for (int it = 0; it < n_iter; it++) {
        float4 nxi, nxp;
        if (it + 1 < n_iter) {
            nxi = pxi[E4];
            nxp = pxp[E4];
        }
        pxi += E4; pxp += E4;

        float4 d;
        d.x = xi.x - xp.x; d.y = xi.y - xp.y;
        d.z = xi.z - xp.z; d.w = xi.w - xp.w;

        #pragma unroll
        for (int p = 0; p < NPASS; p++) {
            float4 o;
            o.x = fmaf(s[p].x, d.x, xp.x);
            o.y = fmaf(s[p].y, d.y, xp.y);
            o.z = fmaf(s[p].z, d.z, xp.z);
            o.w = fmaf(s[p].w, d.w, xp.w);
            // write-once output: streaming store, evict-first in L2
            __stcs(po + p * (WARPS * E4), o);
        }
        po += (LL * E4);   // next i: advance one L-block

        xi = nxi; xp = nxp;
    }
}

// ---------------------------------------------------------------------------
extern "C" void kernel_launch(void* const* d_in, const int* in_sizes, int n_in,
                              void* d_out, int out_size) {
    const float* x  = (const float*)d_in[0];  // (16,192,128) f32
    const float* W  = (const float*)d_in[1];  // (2,1) f32
    const float* bv = (const float*)d_in[2];  // (2,) f32
    float* out = (float*)d_out;               // (16,31898,128) f32

    dim3 grid(ICH, LSPLITS, BB);   // 14 x 12 x 16 = 2688 CTAs
    fused_kernel<<<grid, TPB>>>(x, W, bv, out);
}